// round 10
// baseline (speedup 1.0000x reference)
#include <cuda_runtime.h>
#include <cstdint>
#include <math.h>

// ---------------- output offsets ----------------
#define O1 4194304
#define O2 4243456
#define O3 4276224

// ---------------- smem layout (float indices) ----------------
// GEMM1 staging stride 40 (== 8 mod 32 banks): conflict-free LDS.64 frags.
// sWO stride 72 (== 8 mod 32): conflict-free B-fragment loads.
// sH  stride 72: conflict-free epilogue A-fragment loads (register-staged).
// sU/sV stride 68 (== 4 mod 32): kept — ao MMA's column-indexed scalar
// loads (bank = 8*lc + lg) are conflict-free at 68 and dominate.
#define SWO_OFF 0        // w_out tf32 [64][72]   (4608)
#define B0Y_OFF 4608     // y chunk buf0 [128][40]
#define B1Y_OFF 9728     // y chunk buf1 [128][40]
#define B0W_OFF 14848    // w chunk buf0 [128][40]
#define B1W_OFF 19968    // w chunk buf1 [128][40]
#define SU_OFF  4608     // phase2: u fp32 [128][68]
#define SV_OFF  13312    // phase2: v fp32 [128][68]
#define SH_OFF  4608     // phase3: h tf32 [128][72] (overlaps retired sU)
#define SMEM_FLOATS 25088
#define SMEM_BYTES (SMEM_FLOATS * 4)

#define NPART 512

// ---------------- device scratch ----------------
__device__ float  g_aoPart[NPART * 4096];
__device__ float  g_ao[4096];
__device__ float2 g_rowstats[1344];

__device__ __forceinline__ float silu_f(float v) {
    return __fdividef(v, 1.0f + __expf(-v));
}
__device__ __forceinline__ uint32_t f2tf32(float f) {
    uint32_t r; asm("cvt.rna.tf32.f32 %0, %1;" : "=r"(r) : "f"(f)); return r;
}
__device__ __forceinline__ float f2tf32f(float f) {
    return __uint_as_float(f2tf32(f));
}
__device__ __forceinline__ void mma_tf32(float c[4],
    uint32_t a0, uint32_t a1, uint32_t a2, uint32_t a3,
    uint32_t b0, uint32_t b1)
{
    asm volatile(
        "mma.sync.aligned.m16n8k8.row.col.f32.tf32.tf32.f32 "
        "{%0,%1,%2,%3},{%4,%5,%6,%7},{%8,%9},{%0,%1,%2,%3};"
        : "+f"(c[0]), "+f"(c[1]), "+f"(c[2]), "+f"(c[3])
        : "r"(a0), "r"(a1), "r"(a2), "r"(a3), "r"(b0), "r"(b1));
}

// no-op kernel: shifts ncu's capture (-s 5 -c 1) so the 6th launch is kA
__global__ void kNop() {}

// =====================================================================
// Kernel A: 128-token tile per CTA, tf32 mma.sync, K=32 double-buffered
// chunks, conflict-free staging, 2 CTAs/SM, 512 CTAs.
// =====================================================================
__global__ __launch_bounds__(256, 2)
void kA(const float* __restrict__ x, const float* __restrict__ y,
        const float* __restrict__ w_swiglu, const float* __restrict__ w_out,
        float* __restrict__ out)
{
    extern __shared__ float sm[];
    const int tid = threadIdx.x;
    const int lid = tid & 31;
    const int wid = tid >> 5;
    const int lg  = lid >> 2;       // 0..7
    const int lc  = lid & 3;        // 0..3
    const int wm  = wid & 1;        // 2 warps over M
    const int wn  = wid >> 1;       // 4 warps over N
    const int tok0 = blockIdx.x * 128;

    const float4* yf4 = reinterpret_cast<const float4*>(y);
    const float4* wf4 = reinterpret_cast<const float4*>(w_swiglu);

    // ---- load w_out -> sWO (tf32) [64][72] ----
    float* sWO = sm + SWO_OFF;
    #pragma unroll
    for (int r = 0; r < 4; r++) {
        int i = tid + r * 256;              // 0..1023
        int e = i >> 4, d4 = (i & 15) << 2;
        float4 wv = reinterpret_cast<const float4*>(w_out)[i];
        *reinterpret_cast<float4*>(&sWO[e * 72 + d4]) =
            make_float4(f2tf32f(wv.x), f2tf32f(wv.y), f2tf32f(wv.z), f2tf32f(wv.w));
    }

    // ================= GEMM1: uv = y @ w_swiglu^T, K=256 in 8 chunks of 32 =====
    float acc[4][4][4];
    #pragma unroll
    for (int a = 0; a < 4; a++)
        #pragma unroll
        for (int b = 0; b < 4; b++)
            #pragma unroll
            for (int k = 0; k < 4; k++) acc[a][b][k] = 0.f;

    float* const bufY[2] = { sm + B0Y_OFF, sm + B1Y_OFF };
    float* const bufW[2] = { sm + B0W_OFF, sm + B1W_OFF };

    const int ldrow = tid >> 3;             // 0..31
    const int ldc4  = tid & 7;              // float4 col within 32-chunk

    float4 ry[4], rw[4];

    // prefetch + store chunk 0
    #pragma unroll
    for (int r = 0; r < 4; r++) {
        int row = ldrow + r * 32;
        ry[r] = yf4[(size_t)(tok0 + row) * 64 + ldc4];
        rw[r] = wf4[(size_t)row * 64 + ldc4];
    }
    #pragma unroll
    for (int r = 0; r < 4; r++) {
        int row = ldrow + r * 32;
        *reinterpret_cast<float4*>(&bufY[0][row * 40 + ldc4 * 4]) =
            make_float4(f2tf32f(ry[r].x), f2tf32f(ry[r].y), f2tf32f(ry[r].z), f2tf32f(ry[r].w));
        *reinterpret_cast<float4*>(&bufW[0][row * 40 + ldc4 * 4]) =
            make_float4(f2tf32f(rw[r].x), f2tf32f(rw[r].y), f2tf32f(rw[r].z), f2tf32f(rw[r].w));
    }
    __syncthreads();

    #pragma unroll
    for (int c = 0; c < 8; c++) {
        if (c < 7) {
            #pragma unroll
            for (int r = 0; r < 4; r++) {
                int row = ldrow + r * 32;
                ry[r] = yf4[(size_t)(tok0 + row) * 64 + (c + 1) * 8 + ldc4];
                rw[r] = wf4[(size_t)row * 64 + (c + 1) * 8 + ldc4];
            }
        }
        const float* bY = bufY[c & 1];
        const float* bW = bufW[c & 1];
        #pragma unroll
        for (int ks = 0; ks < 4; ks++) {
            const int kk = ks * 8 + 2 * lc;
            uint32_t A[4][4];
            #pragma unroll
            for (int mt = 0; mt < 4; mt++) {
                const float* p = &bY[(wm * 64 + mt * 16 + lg) * 40 + kk];
                float2 a0 = *reinterpret_cast<const float2*>(p);
                float2 a1 = *reinterpret_cast<const float2*>(p + 8 * 40);
                A[mt][0] = __float_as_uint(a0.x); A[mt][2] = __float_as_uint(a0.y);
                A[mt][1] = __float_as_uint(a1.x); A[mt][3] = __float_as_uint(a1.y);
            }
            uint32_t B[4][2];
            #pragma unroll
            for (int nt = 0; nt < 4; nt++) {
                float2 bv = *reinterpret_cast<const float2*>(&bW[(wn * 32 + nt * 8 + lg) * 40 + kk]);
                B[nt][0] = __float_as_uint(bv.x); B[nt][1] = __float_as_uint(bv.y);
            }
            #pragma unroll
            for (int mt = 0; mt < 4; mt++)
                #pragma unroll
                for (int nt = 0; nt < 4; nt++)
                    mma_tf32(acc[mt][nt], A[mt][0], A[mt][1], A[mt][2], A[mt][3],
                             B[nt][0], B[nt][1]);
        }
        if (c < 7) {
            float* dY = bufY[(c + 1) & 1];
            float* dW = bufW[(c + 1) & 1];
            #pragma unroll
            for (int r = 0; r < 4; r++) {
                int row = ldrow + r * 32;
                *reinterpret_cast<float4*>(&dY[row * 40 + ldc4 * 4]) =
                    make_float4(f2tf32f(ry[r].x), f2tf32f(ry[r].y), f2tf32f(ry[r].z), f2tf32f(ry[r].w));
                *reinterpret_cast<float4*>(&dW[row * 40 + ldc4 * 4]) =
                    make_float4(f2tf32f(rw[r].x), f2tf32f(rw[r].y), f2tf32f(rw[r].z), f2tf32f(rw[r].w));
            }
        }
        __syncthreads();
    }

    // ---- store uv fragments -> sU (fp32), sV (fp32) ----
    float* sU = sm + SU_OFF;    // [128][68]
    float* sV = sm + SV_OFF;    // [128][68]
    {
        float* dst = (wn < 2) ? sU : sV;
        const int cbase = (wn & 1) * 32;
        #pragma unroll
        for (int mt = 0; mt < 4; mt++) {
            int row = wm * 64 + mt * 16 + lg;
            #pragma unroll
            for (int nt = 0; nt < 4; nt++) {
                int cb = cbase + nt * 8 + 2 * lc;
                *reinterpret_cast<float2*>(&dst[row * 68 + cb]) =
                    make_float2(acc[mt][nt][0], acc[mt][nt][1]);
                *reinterpret_cast<float2*>(&dst[(row + 8) * 68 + cb]) =
                    make_float2(acc[mt][nt][2], acc[mt][nt][3]);
            }
        }
    }

    // prefetch x fragments (hide LDG latency behind ao MMA)
    float2 xr[4][2][2];
    #pragma unroll
    for (int mt = 0; mt < 4; mt++)
        #pragma unroll
        for (int nt = 0; nt < 2; nt++) {
            int row = wm * 64 + mt * 16 + lg;
            int col = wn * 16 + nt * 8 + 2 * lc;
            xr[mt][nt][0] = *reinterpret_cast<const float2*>(&x[(size_t)(tok0 + row) * 64 + col]);
            xr[mt][nt][1] = *reinterpret_cast<const float2*>(&x[(size_t)(tok0 + row + 8) * 64 + col]);
        }
    __syncthreads();

    // ================= ao MMA: ao[d][e] = sum_t u[t][d] v[t][e] ================
    float acc3[2][2][4];
    #pragma unroll
    for (int a = 0; a < 2; a++)
        #pragma unroll
        for (int b = 0; b < 2; b++)
            #pragma unroll
            for (int k = 0; k < 4; k++) acc3[a][b][k] = 0.f;

    #pragma unroll
    for (int ks = 0; ks < 16; ks++) {
        const int kk = ks * 8;
        const int t0 = kk + 2 * lc;
        const int t1 = kk + 2 * lc + 1;
        uint32_t A[2][4];
        #pragma unroll
        for (int mt = 0; mt < 2; mt++) {
            int rb = wm * 32 + mt * 16;
            A[mt][0] = f2tf32(sU[t0 * 68 + rb + lg]);
            A[mt][1] = f2tf32(sU[t0 * 68 + rb + lg + 8]);
            A[mt][2] = f2tf32(sU[t1 * 68 + rb + lg]);
            A[mt][3] = f2tf32(sU[t1 * 68 + rb + lg + 8]);
        }
        uint32_t B[2][2];
        #pragma unroll
        for (int nt = 0; nt < 2; nt++) {
            int nb = wn * 16 + nt * 8;
            B[nt][0] = f2tf32(sV[t0 * 68 + nb + lg]);
            B[nt][1] = f2tf32(sV[t1 * 68 + nb + lg]);
        }
        #pragma unroll
        for (int mt = 0; mt < 2; mt++)
            #pragma unroll
            for (int nt = 0; nt < 2; nt++)
                mma_tf32(acc3[mt][nt], A[mt][0], A[mt][1], A[mt][2], A[mt][3],
                         B[nt][0], B[nt][1]);
    }

    // write ao partials
    {
        float* dst = g_aoPart + (size_t)blockIdx.x * 4096;
        #pragma unroll
        for (int mt = 0; mt < 2; mt++)
            #pragma unroll
            for (int nt = 0; nt < 2; nt++) {
                int row = wm * 32 + mt * 16 + lg;
                int col = wn * 16 + nt * 8 + 2 * lc;
                *reinterpret_cast<float2*>(&dst[row * 64 + col]) =
                    make_float2(acc3[mt][nt][0], acc3[mt][nt][1]);
                *reinterpret_cast<float2*>(&dst[(row + 8) * 64 + col]) =
                    make_float2(acc3[mt][nt][2], acc3[mt][nt][3]);
            }
    }
    __syncthreads();    // all ao reads of sU/sV done

    // ---- h = u * silu(v): stage in regs, store to sH stride 72 ----
    float* sH = sm + SH_OFF;    // [128][72] (overlaps retired sU region)
    float4 hreg[8];
    #pragma unroll
    for (int r = 0; r < 8; r++) {
        int i = tid + r * 256;
        int t = i >> 4, d4 = (i & 15) << 2;
        float4 u4 = *reinterpret_cast<const float4*>(&sU[t * 68 + d4]);
        float4 v4 = *reinterpret_cast<const float4*>(&sV[t * 68 + d4]);
        hreg[r] = make_float4(
            f2tf32f(u4.x * silu_f(v4.x)), f2tf32f(u4.y * silu_f(v4.y)),
            f2tf32f(u4.z * silu_f(v4.z)), f2tf32f(u4.w * silu_f(v4.w)));
    }
    __syncthreads();    // all reads done before overwrite
    #pragma unroll
    for (int r = 0; r < 8; r++) {
        int i = tid + r * 256;
        int t = i >> 4, d4 = (i & 15) << 2;
        *reinterpret_cast<float4*>(&sH[t * 72 + d4]) = hreg[r];
    }
    __syncthreads();

    // ================= Epilogue MMA: y_part = h @ w_out^T ======================
    float acc2[4][2][4];
    #pragma unroll
    for (int a = 0; a < 4; a++)
        #pragma unroll
        for (int b = 0; b < 2; b++)
            #pragma unroll
            for (int k = 0; k < 4; k++) acc2[a][b][k] = 0.f;

    #pragma unroll
    for (int ks = 0; ks < 8; ks++) {
        const int kk = ks * 8 + 2 * lc;
        uint32_t A[4][4];
        #pragma unroll
        for (int mt = 0; mt < 4; mt++) {
            const float* p = &sH[(wm * 64 + mt * 16 + lg) * 72 + kk];
            float2 a0 = *reinterpret_cast<const float2*>(p);
            float2 a1 = *reinterpret_cast<const float2*>(p + 8 * 72);
            A[mt][0] = __float_as_uint(a0.x); A[mt][2] = __float_as_uint(a0.y);
            A[mt][1] = __float_as_uint(a1.x); A[mt][3] = __float_as_uint(a1.y);
        }
        uint32_t B[2][2];
        #pragma unroll
        for (int nt = 0; nt < 2; nt++) {
            float2 bv = *reinterpret_cast<const float2*>(&sWO[(wn * 16 + nt * 8 + lg) * 72 + kk]);
            B[nt][0] = __float_as_uint(bv.x); B[nt][1] = __float_as_uint(bv.y);
        }
        #pragma unroll
        for (int mt = 0; mt < 4; mt++)
            #pragma unroll
            for (int nt = 0; nt < 2; nt++)
                mma_tf32(acc2[mt][nt], A[mt][0], A[mt][1], A[mt][2], A[mt][3],
                         B[nt][0], B[nt][1]);
    }

    // write y_out = x + y_part
    #pragma unroll
    for (int mt = 0; mt < 4; mt++)
        #pragma unroll
        for (int nt = 0; nt < 2; nt++) {
            int row = wm * 64 + mt * 16 + lg;
            int col = wn * 16 + nt * 8 + 2 * lc;
            size_t o0 = (size_t)(tok0 + row) * 64 + col;
            size_t o1 = (size_t)(tok0 + row + 8) * 64 + col;
            *reinterpret_cast<float2*>(&out[o0]) =
                make_float2(xr[mt][nt][0].x + acc2[mt][nt][0], xr[mt][nt][0].y + acc2[mt][nt][1]);
            *reinterpret_cast<float2*>(&out[o1]) =
                make_float2(xr[mt][nt][1].x + acc2[mt][nt][2], xr[mt][nt][1].y + acc2[mt][nt][3]);
        }
}

// =====================================================================
// Kernel B: reduce ao partials (high MLP), /64, per-row rms-norm
// =====================================================================
__global__ __launch_bounds__(256)
void kB()
{
    __shared__ float red[4][64];
    __shared__ float tmp[2];
    const int d = blockIdx.x;           // 64 blocks
    const int e = threadIdx.x & 63;
    const int s = threadIdx.x >> 6;     // 4 partial groups of 128

    float sum = 0.f;
    const float* p = &g_aoPart[(size_t)(s * 128) * 4096 + d * 64 + e];
    #pragma unroll 16
    for (int b = 0; b < 128; b++) sum += p[(size_t)b * 4096];
    red[s][e] = sum;
    __syncthreads();

    if (threadIdx.x < 64) {
        float S = (red[0][threadIdx.x] + red[1][threadIdx.x]) +
                  (red[2][threadIdx.x] + red[3][threadIdx.x]);
        S *= (1.0f / 64.0f);
        red[0][threadIdx.x] = S;
        float q = S * S;
        #pragma unroll
        for (int o = 16; o > 0; o >>= 1) q += __shfl_down_sync(0xffffffff, q, o);
        if ((threadIdx.x & 31) == 0) tmp[threadIdx.x >> 5] = q;
    }
    __syncthreads();
    if (threadIdx.x < 64) {
        float ms = (tmp[0] + tmp[1]) * (1.0f / 64.0f) + 1.1920929e-07f;
        g_ao[d * 64 + threadIdx.x] = red[0][threadIdx.x] * rsqrtf(ms);
    }
}

// =====================================================================
// Kernel C: weight updates (unnormalized) + per-row stats
// =====================================================================
__global__ __launch_bounds__(64)
void kC(const float* __restrict__ w_qkv, const float* __restrict__ w_swiglu,
        const float* __restrict__ w_out, const float* __restrict__ out_w,
        float* __restrict__ out)
{
    const int r = blockIdx.x;
    const int j = threadIdx.x;
    __shared__ float rv[64], nn[64];

    float base;
    if (r < 768)        base = w_qkv[r * 64 + j];
    else if (r < 1280)  base = w_swiglu[j * 512 + (r - 768)];
    else                base = w_out[(r - 1280) * 64 + j];
    rv[j] = base;
    __syncthreads();

    float a = 0.f;
    #pragma unroll 8
    for (int k = 0; k < 64; k++) a += rv[k] * g_ao[k * 64 + j];
    nn[j] = silu_f(a);
    __syncthreads();

    float m = base;
    #pragma unroll 8
    for (int k = 0; k < 64; k++) m += nn[k] * out_w[j * 64 + k];

    if (r < 768)        out[O1 + r * 64 + j] = m;
    else if (r < 1280)  out[O2 + j * 512 + (r - 768)] = m;
    else                out[O3 + (r - 1280) * 64 + j] = m;

    float s = m, q = m * m;
    #pragma unroll
    for (int o = 16; o > 0; o >>= 1) {
        s += __shfl_down_sync(0xffffffff, s, o);
        q += __shfl_down_sync(0xffffffff, q, o);
    }
    __shared__ float t4[4];
    if ((j & 31) == 0) { t4[j >> 5] = s; t4[2 + (j >> 5)] = q; }
    __syncthreads();
    if (j == 0) g_rowstats[r] = make_float2(t4[0] + t4[1], t4[2] + t4[3]);
}

// =====================================================================
// Kernel DE: per-matrix scale (redundant per block) + scale sweep
// =====================================================================
__global__ __launch_bounds__(1024)
void kDE(const float* __restrict__ tao, float* __restrict__ out)
{
    const int b = blockIdx.x;
    const int tid = threadIdx.x;
    const int m = (b < 48) ? 0 : ((b < 80) ? 1 : 2);
    const int base = (m == 0) ? 0 : ((m == 1) ? 768 : 1280);
    const int cnt  = (m == 0) ? 768 : ((m == 1) ? 512 : 64);

    float s = 0.f, q = 0.f;
    if (tid < cnt) { float2 v = g_rowstats[base + tid]; s = v.x; q = v.y; }
    #pragma unroll
    for (int o = 16; o > 0; o >>= 1) {
        s += __shfl_down_sync(0xffffffff, s, o);
        q += __shfl_down_sync(0xffffffff, q, o);
    }
    __shared__ float ws[32], wq[32];
    if ((tid & 31) == 0) { ws[tid >> 5] = s; wq[tid >> 5] = q; }
    __syncthreads();
    __shared__ float sc;
    if (tid == 0) {
        float S = 0.f, Q = 0.f;
        #pragma unroll
        for (int i = 0; i < 32; i++) { S += ws[i]; Q += wq[i]; }
        float n      = (m == 0) ? 49152.f : ((m == 1) ? 32768.f : 4096.f);
        float target = (m == 0) ? 0.125f : 0.0625f;
        float var = (Q - S * S / n) / (n - 1.f);
        var = fmaxf(var, 0.f);
        float sd = sqrtf(var);
        float gv = fminf(fmaxf(fabsf(tao[m]), 1e-8f), 1.0f);
        sc = target / (sd + 1e-8f) * gv;
    }
    __syncthreads();
    int i = b * 1024 + tid;
    out[O1 + i] *= sc;
}

// =====================================================================
extern "C" void kernel_launch(void* const* d_in, const int* in_sizes, int n_in,
                              void* d_out, int out_size)
{
    const float* x        = (const float*)d_in[0];
    const float* y        = (const float*)d_in[1];
    const float* w_qkv    = (const float*)d_in[2];
    const float* w_swiglu = (const float*)d_in[3];
    const float* w_out    = (const float*)d_in[4];
    const float* out_w    = (const float*)d_in[5];
    const float* tao      = (const float*)d_in[6];
    float* out = (float*)d_out;

    cudaFuncSetAttribute(kA, cudaFuncAttributeMaxDynamicSharedMemorySize, SMEM_BYTES);
    kNop<<<1, 32>>>();   // aligns ncu capture (-s 5 -c 1) onto kA of iter 2
    kA<<<NPART, 256, SMEM_BYTES>>>(x, y, w_swiglu, w_out, out);
    kB<<<64, 256>>>();
    kC<<<1344, 64>>>(w_qkv, w_swiglu, w_out, out_w, out);
    kDE<<<84, 1024>>>(tao, out);
}

// round 12
// speedup vs baseline: 1.2914x; 1.2914x over previous
#include <cuda_runtime.h>
#include <cstdint>
#include <math.h>

// ---------------- output offsets ----------------
#define O1 4194304
#define O2 4243456
#define O3 4276224

// ---------------- smem layout (float indices) ----------------
// GEMM1 staging stride 40 (== 8 mod 32 banks): conflict-free LDS.64 frags.
#define SWO_OFF 0        // w_out tf32 [64][68]              (4352)
#define B0Y_OFF 4352     // y chunk buf0 [128][40]
#define B1Y_OFF 9472     // y chunk buf1 [128][40]
#define B0W_OFF 14592    // w chunk buf0 [128][40]
#define B1W_OFF 19712    // w chunk buf1 [128][40]
#define SU_OFF  4352     // phase2: u fp32 -> h tf32 [128][68]
#define SV_OFF  13056    // phase2: v fp32 [128][68]
#define SMEM_FLOATS 24832
#define SMEM_BYTES (SMEM_FLOATS * 4)

#define NPART 512

// ---------------- device scratch ----------------
__device__ float  g_aoPart[NPART * 4096];
__device__ float  g_ao[4096];
__device__ float2 g_rowstats[1344];

__device__ __forceinline__ float silu_f(float v) {
    return __fdividef(v, 1.0f + __expf(-v));
}
__device__ __forceinline__ uint32_t f2tf32(float f) {
    uint32_t r; asm("cvt.rna.tf32.f32 %0, %1;" : "=r"(r) : "f"(f)); return r;
}
__device__ __forceinline__ float f2tf32f(float f) {
    return __uint_as_float(f2tf32(f));
}
__device__ __forceinline__ void mma_tf32(float c[4],
    uint32_t a0, uint32_t a1, uint32_t a2, uint32_t a3,
    uint32_t b0, uint32_t b1)
{
    asm volatile(
        "mma.sync.aligned.m16n8k8.row.col.f32.tf32.tf32.f32 "
        "{%0,%1,%2,%3},{%4,%5,%6,%7},{%8,%9},{%0,%1,%2,%3};"
        : "+f"(c[0]), "+f"(c[1]), "+f"(c[2]), "+f"(c[3])
        : "r"(a0), "r"(a1), "r"(a2), "r"(a3), "r"(b0), "r"(b1));
}

// =====================================================================
// Kernel A (R9 best, verbatim): 128-token tile per CTA, tf32 mma.sync,
// K=32 double-buffered chunks (stride-40 staging), 2 CTAs/SM, 512 CTAs.
// =====================================================================
__global__ __launch_bounds__(256, 2)
void kA(const float* __restrict__ x, const float* __restrict__ y,
        const float* __restrict__ w_swiglu, const float* __restrict__ w_out,
        float* __restrict__ out)
{
    extern __shared__ float sm[];
    const int tid = threadIdx.x;
    const int lid = tid & 31;
    const int wid = tid >> 5;
    const int lg  = lid >> 2;       // 0..7
    const int lc  = lid & 3;        // 0..3
    const int wm  = wid & 1;        // 2 warps over M
    const int wn  = wid >> 1;       // 4 warps over N
    const int tok0 = blockIdx.x * 128;

    const float4* yf4 = reinterpret_cast<const float4*>(y);
    const float4* wf4 = reinterpret_cast<const float4*>(w_swiglu);

    // ---- load w_out -> sWO (tf32) [64][68] ----
    float* sWO = sm + SWO_OFF;
    #pragma unroll
    for (int r = 0; r < 4; r++) {
        int i = tid + r * 256;              // 0..1023
        int e = i >> 4, d4 = (i & 15) << 2;
        float4 wv = reinterpret_cast<const float4*>(w_out)[i];
        *reinterpret_cast<float4*>(&sWO[e * 68 + d4]) =
            make_float4(f2tf32f(wv.x), f2tf32f(wv.y), f2tf32f(wv.z), f2tf32f(wv.w));
    }

    // ================= GEMM1: uv = y @ w_swiglu^T, K=256 in 8 chunks of 32 =====
    float acc[4][4][4];
    #pragma unroll
    for (int a = 0; a < 4; a++)
        #pragma unroll
        for (int b = 0; b < 4; b++)
            #pragma unroll
            for (int k = 0; k < 4; k++) acc[a][b][k] = 0.f;

    float* const bufY[2] = { sm + B0Y_OFF, sm + B1Y_OFF };
    float* const bufW[2] = { sm + B0W_OFF, sm + B1W_OFF };

    const int ldrow = tid >> 3;             // 0..31
    const int ldc4  = tid & 7;              // float4 col within 32-chunk

    float4 ry[4], rw[4];

    // prefetch + store chunk 0
    #pragma unroll
    for (int r = 0; r < 4; r++) {
        int row = ldrow + r * 32;
        ry[r] = yf4[(size_t)(tok0 + row) * 64 + ldc4];
        rw[r] = wf4[(size_t)row * 64 + ldc4];
    }
    #pragma unroll
    for (int r = 0; r < 4; r++) {
        int row = ldrow + r * 32;
        *reinterpret_cast<float4*>(&bufY[0][row * 40 + ldc4 * 4]) =
            make_float4(f2tf32f(ry[r].x), f2tf32f(ry[r].y), f2tf32f(ry[r].z), f2tf32f(ry[r].w));
        *reinterpret_cast<float4*>(&bufW[0][row * 40 + ldc4 * 4]) =
            make_float4(f2tf32f(rw[r].x), f2tf32f(rw[r].y), f2tf32f(rw[r].z), f2tf32f(rw[r].w));
    }
    __syncthreads();

    #pragma unroll
    for (int c = 0; c < 8; c++) {
        if (c < 7) {
            #pragma unroll
            for (int r = 0; r < 4; r++) {
                int row = ldrow + r * 32;
                ry[r] = yf4[(size_t)(tok0 + row) * 64 + (c + 1) * 8 + ldc4];
                rw[r] = wf4[(size_t)row * 64 + (c + 1) * 8 + ldc4];
            }
        }
        const float* bY = bufY[c & 1];
        const float* bW = bufW[c & 1];
        #pragma unroll
        for (int ks = 0; ks < 4; ks++) {
            const int kk = ks * 8 + 2 * lc;
            uint32_t A[4][4];
            #pragma unroll
            for (int mt = 0; mt < 4; mt++) {
                const float* p = &bY[(wm * 64 + mt * 16 + lg) * 40 + kk];
                float2 a0 = *reinterpret_cast<const float2*>(p);
                float2 a1 = *reinterpret_cast<const float2*>(p + 8 * 40);
                A[mt][0] = __float_as_uint(a0.x); A[mt][2] = __float_as_uint(a0.y);
                A[mt][1] = __float_as_uint(a1.x); A[mt][3] = __float_as_uint(a1.y);
            }
            uint32_t B[4][2];
            #pragma unroll
            for (int nt = 0; nt < 4; nt++) {
                float2 bv = *reinterpret_cast<const float2*>(&bW[(wn * 32 + nt * 8 + lg) * 40 + kk]);
                B[nt][0] = __float_as_uint(bv.x); B[nt][1] = __float_as_uint(bv.y);
            }
            #pragma unroll
            for (int mt = 0; mt < 4; mt++)
                #pragma unroll
                for (int nt = 0; nt < 4; nt++)
                    mma_tf32(acc[mt][nt], A[mt][0], A[mt][1], A[mt][2], A[mt][3],
                             B[nt][0], B[nt][1]);
        }
        if (c < 7) {
            float* dY = bufY[(c + 1) & 1];
            float* dW = bufW[(c + 1) & 1];
            #pragma unroll
            for (int r = 0; r < 4; r++) {
                int row = ldrow + r * 32;
                *reinterpret_cast<float4*>(&dY[row * 40 + ldc4 * 4]) =
                    make_float4(f2tf32f(ry[r].x), f2tf32f(ry[r].y), f2tf32f(ry[r].z), f2tf32f(ry[r].w));
                *reinterpret_cast<float4*>(&dW[row * 40 + ldc4 * 4]) =
                    make_float4(f2tf32f(rw[r].x), f2tf32f(rw[r].y), f2tf32f(rw[r].z), f2tf32f(rw[r].w));
            }
        }
        __syncthreads();
    }

    // ---- store uv fragments -> sU (fp32), sV (fp32) ----
    float* sU = sm + SU_OFF;    // [128][68]
    float* sV = sm + SV_OFF;    // [128][68]
    {
        float* dst = (wn < 2) ? sU : sV;
        const int cbase = (wn & 1) * 32;
        #pragma unroll
        for (int mt = 0; mt < 4; mt++) {
            int row = wm * 64 + mt * 16 + lg;
            #pragma unroll
            for (int nt = 0; nt < 4; nt++) {
                int cb = cbase + nt * 8 + 2 * lc;
                *reinterpret_cast<float2*>(&dst[row * 68 + cb]) =
                    make_float2(acc[mt][nt][0], acc[mt][nt][1]);
                *reinterpret_cast<float2*>(&dst[(row + 8) * 68 + cb]) =
                    make_float2(acc[mt][nt][2], acc[mt][nt][3]);
            }
        }
    }

    // prefetch x fragments (hide LDG latency behind ao MMA)
    float2 xr[4][2][2];
    #pragma unroll
    for (int mt = 0; mt < 4; mt++)
        #pragma unroll
        for (int nt = 0; nt < 2; nt++) {
            int row = wm * 64 + mt * 16 + lg;
            int col = wn * 16 + nt * 8 + 2 * lc;
            xr[mt][nt][0] = *reinterpret_cast<const float2*>(&x[(size_t)(tok0 + row) * 64 + col]);
            xr[mt][nt][1] = *reinterpret_cast<const float2*>(&x[(size_t)(tok0 + row + 8) * 64 + col]);
        }
    __syncthreads();

    // ================= ao MMA: ao[d][e] = sum_t u[t][d] v[t][e] ================
    float acc3[2][2][4];
    #pragma unroll
    for (int a = 0; a < 2; a++)
        #pragma unroll
        for (int b = 0; b < 2; b++)
            #pragma unroll
            for (int k = 0; k < 4; k++) acc3[a][b][k] = 0.f;

    #pragma unroll
    for (int ks = 0; ks < 16; ks++) {
        const int kk = ks * 8;
        const int t0 = kk + 2 * lc;
        const int t1 = kk + 2 * lc + 1;
        uint32_t A[2][4];
        #pragma unroll
        for (int mt = 0; mt < 2; mt++) {
            int rb = wm * 32 + mt * 16;
            A[mt][0] = f2tf32(sU[t0 * 68 + rb + lg]);
            A[mt][1] = f2tf32(sU[t0 * 68 + rb + lg + 8]);
            A[mt][2] = f2tf32(sU[t1 * 68 + rb + lg]);
            A[mt][3] = f2tf32(sU[t1 * 68 + rb + lg + 8]);
        }
        uint32_t B[2][2];
        #pragma unroll
        for (int nt = 0; nt < 2; nt++) {
            int nb = wn * 16 + nt * 8;
            B[nt][0] = f2tf32(sV[t0 * 68 + nb + lg]);
            B[nt][1] = f2tf32(sV[t1 * 68 + nb + lg]);
        }
        #pragma unroll
        for (int mt = 0; mt < 2; mt++)
            #pragma unroll
            for (int nt = 0; nt < 2; nt++)
                mma_tf32(acc3[mt][nt], A[mt][0], A[mt][1], A[mt][2], A[mt][3],
                         B[nt][0], B[nt][1]);
    }

    // write ao partials
    {
        float* dst = g_aoPart + (size_t)blockIdx.x * 4096;
        #pragma unroll
        for (int mt = 0; mt < 2; mt++)
            #pragma unroll
            for (int nt = 0; nt < 2; nt++) {
                int row = wm * 32 + mt * 16 + lg;
                int col = wn * 16 + nt * 8 + 2 * lc;
                *reinterpret_cast<float2*>(&dst[row * 64 + col]) =
                    make_float2(acc3[mt][nt][0], acc3[mt][nt][1]);
                *reinterpret_cast<float2*>(&dst[(row + 8) * 64 + col]) =
                    make_float2(acc3[mt][nt][2], acc3[mt][nt][3]);
            }
    }
    __syncthreads();    // all ao reads of sU/sV done

    // ---- h = u * silu(v) IN PLACE over sU (tf32) ----
    #pragma unroll
    for (int r = 0; r < 8; r++) {
        int i = tid + r * 256;
        int t = i >> 4, d4 = (i & 15) << 2;
        float4 u4 = *reinterpret_cast<const float4*>(&sU[t * 68 + d4]);
        float4 v4 = *reinterpret_cast<const float4*>(&sV[t * 68 + d4]);
        *reinterpret_cast<float4*>(&sU[t * 68 + d4]) = make_float4(
            f2tf32f(u4.x * silu_f(v4.x)), f2tf32f(u4.y * silu_f(v4.y)),
            f2tf32f(u4.z * silu_f(v4.z)), f2tf32f(u4.w * silu_f(v4.w)));
    }
    __syncthreads();

    // ================= Epilogue MMA: y_part = h @ w_out^T ======================
    float acc2[4][2][4];
    #pragma unroll
    for (int a = 0; a < 4; a++)
        #pragma unroll
        for (int b = 0; b < 2; b++)
            #pragma unroll
            for (int k = 0; k < 4; k++) acc2[a][b][k] = 0.f;

    const float* sH = sU;
    #pragma unroll
    for (int ks = 0; ks < 8; ks++) {
        const int kk = ks * 8 + 2 * lc;
        uint32_t A[4][4];
        #pragma unroll
        for (int mt = 0; mt < 4; mt++) {
            const float* p = &sH[(wm * 64 + mt * 16 + lg) * 68 + kk];
            float2 a0 = *reinterpret_cast<const float2*>(p);
            float2 a1 = *reinterpret_cast<const float2*>(p + 8 * 68);
            A[mt][0] = __float_as_uint(a0.x); A[mt][2] = __float_as_uint(a0.y);
            A[mt][1] = __float_as_uint(a1.x); A[mt][3] = __float_as_uint(a1.y);
        }
        uint32_t B[2][2];
        #pragma unroll
        for (int nt = 0; nt < 2; nt++) {
            float2 bv = *reinterpret_cast<const float2*>(&sWO[(wn * 16 + nt * 8 + lg) * 68 + kk]);
            B[nt][0] = __float_as_uint(bv.x); B[nt][1] = __float_as_uint(bv.y);
        }
        #pragma unroll
        for (int mt = 0; mt < 4; mt++)
            #pragma unroll
            for (int nt = 0; nt < 2; nt++)
                mma_tf32(acc2[mt][nt], A[mt][0], A[mt][1], A[mt][2], A[mt][3],
                         B[nt][0], B[nt][1]);
    }

    // write y_out = x + y_part
    #pragma unroll
    for (int mt = 0; mt < 4; mt++)
        #pragma unroll
        for (int nt = 0; nt < 2; nt++) {
            int row = wm * 64 + mt * 16 + lg;
            int col = wn * 16 + nt * 8 + 2 * lc;
            size_t o0 = (size_t)(tok0 + row) * 64 + col;
            size_t o1 = (size_t)(tok0 + row + 8) * 64 + col;
            *reinterpret_cast<float2*>(&out[o0]) =
                make_float2(xr[mt][nt][0].x + acc2[mt][nt][0], xr[mt][nt][0].y + acc2[mt][nt][1]);
            *reinterpret_cast<float2*>(&out[o1]) =
                make_float2(xr[mt][nt][1].x + acc2[mt][nt][2], xr[mt][nt][1].y + acc2[mt][nt][3]);
        }
}

// =====================================================================
// Kernel B: reduce ao partials (high MLP), /64, per-row rms-norm
// =====================================================================
__global__ __launch_bounds__(256)
void kB()
{
    __shared__ float red[4][64];
    __shared__ float tmp[2];
    const int d = blockIdx.x;           // 64 blocks
    const int e = threadIdx.x & 63;
    const int s = threadIdx.x >> 6;     // 4 partial groups of 128

    float sum = 0.f;
    const float* p = &g_aoPart[(size_t)(s * 128) * 4096 + d * 64 + e];
    #pragma unroll 16
    for (int b = 0; b < 128; b++) sum += p[(size_t)b * 4096];
    red[s][e] = sum;
    __syncthreads();

    if (threadIdx.x < 64) {
        float S = (red[0][threadIdx.x] + red[1][threadIdx.x]) +
                  (red[2][threadIdx.x] + red[3][threadIdx.x]);
        S *= (1.0f / 64.0f);
        red[0][threadIdx.x] = S;
        float q = S * S;
        #pragma unroll
        for (int o = 16; o > 0; o >>= 1) q += __shfl_down_sync(0xffffffff, q, o);
        if ((threadIdx.x & 31) == 0) tmp[threadIdx.x >> 5] = q;
    }
    __syncthreads();
    if (threadIdx.x < 64) {
        float ms = (tmp[0] + tmp[1]) * (1.0f / 64.0f) + 1.1920929e-07f;
        g_ao[d * 64 + threadIdx.x] = red[0][threadIdx.x] * rsqrtf(ms);
    }
}

// =====================================================================
// Kernel C: weight updates + per-row stats.
//   336 blocks x 256 threads, 4 rows per block. g_ao and out_w staged
//   in smem once per block (coalesced LDG.128, scalar STS to stride-65
//   rows — 65 is odd so vector stores would be misaligned). Both inner
//   products then run on conflict-free LDS + broadcasts; math order
//   identical to the original kC (bit-identical results).
// =====================================================================
__global__ __launch_bounds__(256)
void kC(const float* __restrict__ w_qkv, const float* __restrict__ w_swiglu,
        const float* __restrict__ w_out, const float* __restrict__ out_w,
        float* __restrict__ out)
{
    __shared__ float aoS[64 * 65];   // aoS[k][j] = g_ao[k*64+j]
    __shared__ float woS[64 * 65];   // woS[j][k] = out_w[j*64+k]
    __shared__ float rv[4][64], nn[4][64];
    __shared__ float t16[16];

    const int tid = threadIdx.x;
    const int g = tid >> 6;          // row group 0..3
    const int j = tid & 63;

    // stage g_ao and out_w: coalesced float4 loads, scalar smem stores
    #pragma unroll
    for (int rr = 0; rr < 4; rr++) {
        int i4 = tid + rr * 256;     // float4 index 0..1023
        int row = i4 >> 4, c4 = (i4 & 15) << 2;
        float4 av = reinterpret_cast<const float4*>(g_ao)[i4];
        float* ap = &aoS[row * 65 + c4];
        ap[0] = av.x; ap[1] = av.y; ap[2] = av.z; ap[3] = av.w;
        float4 wv = reinterpret_cast<const float4*>(out_w)[i4];
        float* wp = &woS[row * 65 + c4];
        wp[0] = wv.x; wp[1] = wv.y; wp[2] = wv.z; wp[3] = wv.w;
    }

    const int r = blockIdx.x * 4 + g;    // 0..1343

    float base;
    if (r < 768)        base = w_qkv[r * 64 + j];
    else if (r < 1280)  base = w_swiglu[j * 512 + (r - 768)];
    else                base = w_out[(r - 1280) * 64 + j];
    rv[g][j] = base;
    __syncthreads();

    float a = 0.f;
    #pragma unroll 8
    for (int k = 0; k < 64; k++) a += rv[g][k] * aoS[k * 65 + j];
    nn[g][j] = silu_f(a);
    __syncthreads();

    float m = base;
    #pragma unroll 8
    for (int k = 0; k < 64; k++) m += nn[g][k] * woS[j * 65 + k];

    if (r < 768)        out[O1 + r * 64 + j] = m;
    else if (r < 1280)  out[O2 + j * 512 + (r - 768)] = m;
    else                out[O3 + (r - 1280) * 64 + j] = m;

    // row stats (sum, sumsq) per 64-thread group
    float s = m, q = m * m;
    #pragma unroll
    for (int o = 16; o > 0; o >>= 1) {
        s += __shfl_down_sync(0xffffffff, s, o);
        q += __shfl_down_sync(0xffffffff, q, o);
    }
    if ((j & 31) == 0) {
        t16[g * 4 + (j >> 5) * 2]     = s;
        t16[g * 4 + (j >> 5) * 2 + 1] = q;
    }
    __syncthreads();
    if (j == 0)
        g_rowstats[r] = make_float2(t16[g * 4] + t16[g * 4 + 2],
                                    t16[g * 4 + 1] + t16[g * 4 + 3]);
}

// =====================================================================
// Kernel DE: per-matrix scale (redundant per block) + scale sweep
// =====================================================================
__global__ __launch_bounds__(1024)
void kDE(const float* __restrict__ tao, float* __restrict__ out)
{
    const int b = blockIdx.x;
    const int tid = threadIdx.x;
    const int m = (b < 48) ? 0 : ((b < 80) ? 1 : 2);
    const int base = (m == 0) ? 0 : ((m == 1) ? 768 : 1280);
    const int cnt  = (m == 0) ? 768 : ((m == 1) ? 512 : 64);

    float s = 0.f, q = 0.f;
    if (tid < cnt) { float2 v = g_rowstats[base + tid]; s = v.x; q = v.y; }
    #pragma unroll
    for (int o = 16; o > 0; o >>= 1) {
        s += __shfl_down_sync(0xffffffff, s, o);
        q += __shfl_down_sync(0xffffffff, q, o);
    }
    __shared__ float ws[32], wq[32];
    if ((tid & 31) == 0) { ws[tid >> 5] = s; wq[tid >> 5] = q; }
    __syncthreads();
    __shared__ float sc;
    if (tid == 0) {
        float S = 0.f, Q = 0.f;
        #pragma unroll
        for (int i = 0; i < 32; i++) { S += ws[i]; Q += wq[i]; }
        float n      = (m == 0) ? 49152.f : ((m == 1) ? 32768.f : 4096.f);
        float target = (m == 0) ? 0.125f : 0.0625f;
        float var = (Q - S * S / n) / (n - 1.f);
        var = fmaxf(var, 0.f);
        float sd = sqrtf(var);
        float gv = fminf(fmaxf(fabsf(tao[m]), 1e-8f), 1.0f);
        sc = target / (sd + 1e-8f) * gv;
    }
    __syncthreads();
    int i = b * 1024 + tid;
    out[O1 + i] *= sc;
}

// =====================================================================
extern "C" void kernel_launch(void* const* d_in, const int* in_sizes, int n_in,
                              void* d_out, int out_size)
{
    const float* x        = (const float*)d_in[0];
    const float* y        = (const float*)d_in[1];
    const float* w_qkv    = (const float*)d_in[2];
    const float* w_swiglu = (const float*)d_in[3];
    const float* w_out    = (const float*)d_in[4];
    const float* out_w    = (const float*)d_in[5];
    const float* tao      = (const float*)d_in[6];
    float* out = (float*)d_out;

    cudaFuncSetAttribute(kA, cudaFuncAttributeMaxDynamicSharedMemorySize, SMEM_BYTES);
    kA<<<NPART, 256, SMEM_BYTES>>>(x, y, w_swiglu, w_out, out);
    kB<<<64, 256>>>();
    kC<<<336, 256>>>(w_qkv, w_swiglu, w_out, out_w, out);
    kDE<<<84, 1024>>>(tao, out);
}